// round 11
// baseline (speedup 1.0000x reference)
#include <cuda_runtime.h>
#include <math.h>

typedef unsigned long long ull;

// ---------------- problem constants ----------------
#define Bb   4
#define Cc   64
#define Hh   5
#define Ww   5
#define Kk   3
#define Ee   12
#define NHh  4
#define DHh  3
#define FFf  24
#define HOo  3
#define WOo  3
#define Ll   9
#define Ss   (Bb*Cc*Kk*Kk)       // 2304
#define ROWS (Ss*Ll)             // 20736
#define NC   (Ll*NHh)            // 36
#define YSZ  (Bb*Cc*Hh*Ww)       // 6400

#define DEG  14                  // Taylor degree: pairs j=0..14, moments M_0..M_15

// ---------------- scratch ----------------
__device__ float4 g_ctx[NC*Ss];         // attention output per (combo, s)

// ---------------- packed f32x2 helpers ----------------
__device__ __forceinline__ ull ffma2(ull a, ull b, ull c) {
    ull d; asm("fma.rn.f32x2 %0, %1, %2, %3;" : "=l"(d) : "l"(a), "l"(b), "l"(c)); return d;
}
__device__ __forceinline__ ull pack2(float lo, float hi) {
    ull d; asm("mov.b64 %0, {%1, %2};" : "=l"(d) : "f"(lo), "f"(hi)); return d;
}
__device__ __forceinline__ void unpack2(ull v, float& lo, float& hi) {
    asm("mov.b64 {%0, %1}, %2;" : "=f"(lo), "=f"(hi) : "l"(v));
}
__device__ __forceinline__ float ex2(float x) {
    float r; asm("ex2.approx.f32 %0, %1;" : "=f"(r) : "f"(x)); return r;
}

// ---------------- kernel 1: attention (fused moments + tables + Taylor softmax) ----------------
// grid (36 combos, 18 q-chunks), 128 threads, 1 query/thread.
__global__ void k_attn(const float* __restrict__ x,
                       const float* __restrict__ ce,
                       const float* __restrict__ pe,
                       const float* __restrict__ ipw,
                       const float* __restrict__ ipb,
                       float* __restrict__ y)
{
    __shared__ ulonglong2 sTM[Cc*8];        // per c': 15 pairs {M_j/j!, M_{j+1}/j!} + pad (128B)
    __shared__ float4 sTB[Cc*2];            // per c': {b*log2e, 0}, {v0, 0}
    __shared__ float4 sTA[Cc];              // per c (query side): {a0,a1,a2, gamma}
    __shared__ float  sUW[8];               // {u0,u1,u2, delta, wv0,wv1,wv2, -}

    int combo = blockIdx.x;
    int l = combo >> 2, h = combo & 3;
    int tid = threadIdx.x;
    int oi = l/WOo, oj = l%WOo;
    const unsigned FULL = 0xFFFFFFFFu;

    // zero output once (combo 0 blocks; completes before k_post launch)
    if (combo == 0) {
        for (int i = blockIdx.y*128 + tid; i < YSZ; i += 18*128) y[i] = 0.f;
    }

    // ---- moments: 2 threads per channel, 18 samples each ----
    {
        int ch = tid >> 1, hf = tid & 1;
        float m[16];
        #pragma unroll
        for (int k = 0; k < 16; k++) m[k] = 0.f;

        #pragma unroll
        for (int bb = 0; bb < 2; bb++) {
            int b = hf*2 + bb;
            #pragma unroll
            for (int p = 0; p < 9; p++) {
                float xv = x[((b*Cc + ch)*Hh + (p/3) + oi)*Ww + (p%3) + oj];
                float pw = 1.f;
                #pragma unroll
                for (int k = 0; k < 16; k++) { m[k] += pw; pw *= xv; }
            }
        }
        #pragma unroll
        for (int k = 0; k < 16; k++) m[k] += __shfl_xor_sync(FULL, m[k], 1);

        if (hf == 0) {
            float* dst = (float*)&sTM[ch*8];
            float invf = 1.f;
            #pragma unroll
            for (int j = 0; j <= DEG; j++) {
                if (j > 0) invf /= (float)j;      // 1/j!
                dst[2*j]   = m[j]   * invf;
                dst[2*j+1] = m[j+1] * invf;
            }
            dst[30] = 0.f; dst[31] = 0.f;
        }
    }

    // ---- tables: thread per channel (tid < 64) ----
    const float IS3 = 0.57735026918962576f;
    const float L2E = 1.4426950408889634f;
    if (tid < Cc) {
        int c = tid;
        float rc[Ee];
        #pragma unroll
        for (int f = 0; f < Ee; f++) rc[f] = ce[c*Ee + f] + pe[l*Ee + f];

        float a[3], b[3], v0[3], w[3];
        #pragma unroll
        for (int d = 0; d < 3; d++) {
            const float* Wq = ipw + (3*h + d)*Ee;
            const float* Wk = ipw + (Ee + 3*h + d)*Ee;
            const float* Wv = ipw + (2*Ee + 3*h + d)*Ee;
            float aq = ipb[3*h + d];
            float ak = ipb[Ee + 3*h + d];
            float av = ipb[2*Ee + 3*h + d];
            float uk = 0.f;
            #pragma unroll
            for (int f = 0; f < Ee; f++) {
                aq += Wq[f]*rc[f]; ak += Wk[f]*rc[f]; av += Wv[f]*rc[f];
                uk += Wk[f];
            }
            a[d] = aq*IS3; b[d] = ak; v0[d] = av; w[d] = uk;
        }
        float gamma = a[0]*w[0] + a[1]*w[1] + a[2]*w[2];
        sTA[c] = make_float4(a[0], a[1], a[2], gamma);
        sTB[c*2 + 0] = make_float4(b[0]*L2E, b[1]*L2E, b[2]*L2E, 0.f);
        sTB[c*2 + 1] = make_float4(v0[0], v0[1], v0[2], 0.f);
    } else if (tid == 64) {
        float u[3], w[3], wv[3];
        #pragma unroll
        for (int d = 0; d < 3; d++) {
            float uq = 0.f, uk = 0.f, uv = 0.f;
            #pragma unroll
            for (int f = 0; f < Ee; f++) {
                uq += ipw[(3*h + d)*Ee + f];
                uk += ipw[(Ee + 3*h + d)*Ee + f];
                uv += ipw[(2*Ee + 3*h + d)*Ee + f];
            }
            u[d] = uq*IS3; w[d] = uk; wv[d] = uv;
        }
        sUW[0] = u[0]; sUW[1] = u[1]; sUW[2] = u[2];
        sUW[3] = u[0]*w[0] + u[1]*w[1] + u[2]*w[2];   // delta
        sUW[4] = wv[0]; sUW[5] = wv[1]; sUW[6] = wv[2];
    }
    __syncthreads();

    // ---- per-query main loop ----
    int s = blockIdx.y*128 + tid;
    int bi = s / (Cc*9);
    int rem = s % (Cc*9);
    int c = rem / 9, p = rem % 9;
    float xv = x[((bi*Cc + c)*Hh + (p/3) + oi)*Ww + (p%3) + oj];

    float4 ag = sTA[c];
    float u0 = sUW[0], u1 = sUW[1], u2 = sUW[2], delta = sUW[3];
    float wv0 = sUW[4], wv1 = sUW[5], wv2 = sUW[6];

    float q0 = ag.x + xv*u0;
    float q1 = ag.y + xv*u1;
    float q2 = ag.z + xv*u2;
    float g  = ag.w + xv*delta;             // q~·w
    ull  g2  = pack2(g, g);

    float den = 0.f, o0 = 0.f, o1 = 0.f, o2 = 0.f;

    #pragma unroll 2
    for (int cp = 0; cp < Cc; cp++) {
        float4 bb = sTB[cp*2];
        float4 vv = sTB[cp*2 + 1];
        const ull* Cp = (const ull*)&sTM[cp*8];

        float earg = fmaf(q0, bb.x, fmaf(q1, bb.y, q2*bb.z));   // already *log2e
        float E = ex2(earg);

        ull acc = Cp[DEG];
        #pragma unroll
        for (int j = DEG-1; j >= 0; j--) acc = ffma2(acc, g2, Cp[j]);
        float S0, S1; unpack2(acc, S0, S1);

        float ES0 = E*S0, ES1 = E*S1;
        den += ES0;
        o0 = fmaf(ES1, wv0, fmaf(ES0, vv.x, o0));
        o1 = fmaf(ES1, wv1, fmaf(ES0, vv.y, o1));
        o2 = fmaf(ES1, wv2, fmaf(ES0, vv.z, o2));
    }

    float inv = 1.f / den;
    g_ctx[combo*Ss + s] = make_float4(o0*inv, o1*inv, o2*inv, 0.f);
}

// ---------------- kernel 2: out_proj + LN1 + FFN + LN2 + linear + fold ----------------
// FOUR threads per row: features split 3/3/3/3; reductions via 2-level shfl_xor (quad-aligned).
__global__ void k_post(const float* __restrict__ x,
                       const float* __restrict__ cemb, const float* __restrict__ pemb,
                       const float* __restrict__ wo, const float* __restrict__ bo,
                       const float* __restrict__ g1, const float* __restrict__ b1,
                       const float* __restrict__ f1w, const float* __restrict__ f1b,
                       const float* __restrict__ f2w, const float* __restrict__ f2b,
                       const float* __restrict__ g2, const float* __restrict__ b2,
                       const float* __restrict__ lw, const float* __restrict__ lb,
                       float* __restrict__ y)
{
    __shared__ float swo[Ee*Ee], sbo[Ee], sg1[Ee], sb1[Ee];
    __shared__ float s1[FFf*Ee], s1b[FFf], s2[Ee*FFf], s2b[Ee];
    __shared__ float sg2[Ee], sb2[Ee], slw[Ee], slb;
    for (int i = threadIdx.x; i < Ee*Ee; i += blockDim.x) swo[i] = wo[i];
    for (int i = threadIdx.x; i < FFf*Ee; i += blockDim.x) { s1[i] = f1w[i]; s2[i] = f2w[i]; }
    if (threadIdx.x < FFf) s1b[threadIdx.x] = f1b[threadIdx.x];
    if (threadIdx.x < Ee) {
        sbo[threadIdx.x] = bo[threadIdx.x];
        sg1[threadIdx.x] = g1[threadIdx.x];
        sb1[threadIdx.x] = b1[threadIdx.x];
        s2b[threadIdx.x] = f2b[threadIdx.x];
        sg2[threadIdx.x] = g2[threadIdx.x];
        sb2[threadIdx.x] = b2[threadIdx.x];
        slw[threadIdx.x] = lw[threadIdx.x];
    }
    if (threadIdx.x == 0) slb = lb[0];
    __syncthreads();

    int gt = blockIdx.x*blockDim.x + threadIdx.x;
    int row = gt >> 2;                  // l-major: row = l*Ss + s
    int q   = gt & 3;                   // quad lane
    int l = row / Ss, s = row % Ss;
    const unsigned FULL = 0xFFFFFFFFu;

    // gather full ctx (12) — quad lanes broadcast from L1
    float cx[Ee];
    #pragma unroll
    for (int h = 0; h < NHh; h++) {
        float4 o = g_ctx[(l*NHh + h)*Ss + s];
        cx[h*3] = o.x; cx[h*3+1] = o.y; cx[h*3+2] = o.z;
    }

    int bi = s / (Cc*9);
    int rem = s % (Cc*9);
    int c = rem / 9, p = rem % 9;
    int pi = p/3, pj = p%3;
    int oi = l/WOo, oj = l%WOo;
    float xv = x[((bi*Cc + c)*Hh + pi + oi)*Ww + pj + oj];

    int ebase = q*3;

    // ---- out_proj + residual (own 3 outputs) ----
    float t[3];
    #pragma unroll
    for (int eo = 0; eo < 3; eo++) {
        int e = ebase + eo;
        float acc = sbo[e];
        #pragma unroll
        for (int f = 0; f < Ee; f++) acc += cx[f] * swo[e*Ee + f];
        t[eo] = (__ldg(&cemb[c*Ee + e]) + __ldg(&pemb[l*Ee + e]) + xv) + acc;
    }

    // ---- LN1 (quad reduction) ----
    float sl = t[0] + t[1] + t[2];
    sl += __shfl_xor_sync(FULL, sl, 1);
    sl += __shfl_xor_sync(FULL, sl, 2);
    float mu = sl * (1.f/Ee);
    float vl = 0.f;
    #pragma unroll
    for (int eo = 0; eo < 3; eo++) { float d = t[eo]-mu; vl += d*d; }
    vl += __shfl_xor_sync(FULL, vl, 1);
    vl += __shfl_xor_sync(FULL, vl, 2);
    float rs = rsqrtf(vl*(1.f/Ee) + 1e-5f);

    float h1[3];
    #pragma unroll
    for (int eo = 0; eo < 3; eo++) {
        int e = ebase + eo;
        h1[eo] = (t[eo]-mu)*rs*sg1[e] + sb1[e];
    }

    // ---- FF1: partial-dot own 3 features for all 24 hidden; butterfly-reduce ----
    float hid[FFf];
    #pragma unroll
    for (int f = 0; f < FFf; f++) {
        float pd = h1[0]*s1[f*Ee + ebase] + h1[1]*s1[f*Ee + ebase + 1] + h1[2]*s1[f*Ee + ebase + 2];
        pd += __shfl_xor_sync(FULL, pd, 1);
        pd += __shfl_xor_sync(FULL, pd, 2);
        hid[f] = fmaxf(pd + s1b[f], 0.f);
    }

    // ---- FF2 + residual (own 3 outputs, full hidden) ----
    float t2[3];
    #pragma unroll
    for (int eo = 0; eo < 3; eo++) {
        int e = ebase + eo;
        float acc = s2b[e];
        #pragma unroll
        for (int f = 0; f < FFf; f++) acc += hid[f] * s2[e*FFf + f];
        t2[eo] = h1[eo] + acc;
    }

    // ---- LN2 (quad reduction) ----
    float sl2 = t2[0] + t2[1] + t2[2];
    sl2 += __shfl_xor_sync(FULL, sl2, 1);
    sl2 += __shfl_xor_sync(FULL, sl2, 2);
    float mu2 = sl2 * (1.f/Ee);
    float vl2 = 0.f;
    #pragma unroll
    for (int eo = 0; eo < 3; eo++) { float d = t2[eo]-mu2; vl2 += d*d; }
    vl2 += __shfl_xor_sync(FULL, vl2, 1);
    vl2 += __shfl_xor_sync(FULL, vl2, 2);
    float rs2 = rsqrtf(vl2*(1.f/Ee) + 1e-5f);

    // ---- final linear (quad-reduced dot) ----
    float pl = 0.f;
    #pragma unroll
    for (int eo = 0; eo < 3; eo++) {
        int e = ebase + eo;
        pl += ((t2[eo]-mu2)*rs2*sg2[e] + sb2[e]) * slw[e];
    }
    pl += __shfl_xor_sync(FULL, pl, 1);
    pl += __shfl_xor_sync(FULL, pl, 2);

    if (q == 0) {
        float proj = slb + pl;
        atomicAdd(&y[((bi*Cc + c)*Hh + (pi+oi))*Ww + (pj+oj)], proj);
    }
}

// ---------------- launch ----------------
extern "C" void kernel_launch(void* const* d_in, const int* in_sizes, int n_in,
                              void* d_out, int out_size)
{
    const float* x    = (const float*)d_in[0];
    const float* ce   = (const float*)d_in[1];
    const float* pe   = (const float*)d_in[2];
    const float* ipw  = (const float*)d_in[3];
    const float* ipb  = (const float*)d_in[4];
    const float* opw  = (const float*)d_in[5];
    const float* opb  = (const float*)d_in[6];
    const float* ln1w = (const float*)d_in[7];
    const float* ln1b = (const float*)d_in[8];
    const float* f1w  = (const float*)d_in[9];
    const float* f1b  = (const float*)d_in[10];
    const float* f2w  = (const float*)d_in[11];
    const float* f2b  = (const float*)d_in[12];
    const float* ln2w = (const float*)d_in[13];
    const float* ln2b = (const float*)d_in[14];
    const float* lw   = (const float*)d_in[15];
    const float* lb   = (const float*)d_in[16];
    float* y = (float*)d_out;

    dim3 agrid(NC, Ss/128);
    k_attn<<<agrid, 128>>>(x, ce, pe, ipw, ipb, y);
    k_post<<<ROWS*4/128, 128>>>(x, ce, pe, opw, opb, ln1w, ln1b,
                                f1w, f1b, f2w, f2b, ln2w, ln2b, lw, lb, y);
}